// round 5
// baseline (speedup 1.0000x reference)
#include <cuda_runtime.h>

#define NN 50000
#define NE 800000
#define ET (NE + NN)
#define NC 64
#define NCHUNK ((NN + 1023) / 1024)

typedef unsigned long long u64;

// ---------------------------------------------------------------------------
// Static device scratch (allocation-free rule).
// ---------------------------------------------------------------------------
__device__ float g_hA[NN * NC];
__device__ float g_hB[NN * NC];
__device__ int   g_csrc[ET];          // CSR: src node per edge, grouped by dst
__device__ int   g_rowptr[NN + 1];
__device__ int   g_cnt[NN];           // zero at entry (zeroed by layer2 epilogue)
__device__ int   g_cur[NN];
__device__ int   g_agg[NCHUNK];       // decoupled-lookback state
__device__ int   g_inc[NCHUNK];
__device__ int   g_flag[NCHUNK];      // zeroed by k_hist each call

// ---------------------------------------------------------------------------
// Packed f32x2 helpers (SASS FFMA2/FADD2 — PTX-only)
// ---------------------------------------------------------------------------
__device__ __forceinline__ u64 PK(float lo, float hi) {
    u64 r; asm("mov.b64 %0,{%1,%2};" : "=l"(r) : "f"(lo), "f"(hi)); return r;
}
__device__ __forceinline__ void UPK(u64 v, float& lo, float& hi) {
    asm("mov.b64 {%0,%1},%2;" : "=f"(lo), "=f"(hi) : "l"(v));
}
__device__ __forceinline__ u64 FADD2(u64 a, u64 b) {
    u64 r; asm("add.rn.f32x2 %0,%1,%2;" : "=l"(r) : "l"(a), "l"(b)); return r;
}
__device__ __forceinline__ u64 FMUL2(u64 a, u64 b) {
    u64 r; asm("mul.rn.f32x2 %0,%1,%2;" : "=l"(r) : "l"(a), "l"(b)); return r;
}
__device__ __forceinline__ u64 FFMA2(u64 a, u64 b, u64 c) {
    u64 r; asm("fma.rn.f32x2 %0,%1,%2,%3;" : "=l"(r) : "l"(a), "l"(b), "l"(c)); return r;
}
__device__ __forceinline__ u64 FABS2(u64 a) { return a & 0x7FFFFFFF7FFFFFFFULL; }

// ---------------------------------------------------------------------------
// CSR build: hist -> single-kernel scan (decoupled lookback) -> scatter
// ---------------------------------------------------------------------------
__global__ void k_hist(const int* __restrict__ ei) {
    int e = blockIdx.x * blockDim.x + threadIdx.x;
    if (e < NCHUNK) g_flag[e] = 0;          // reset lookback state for k_scan
    if (e >= ET) return;
    int dst = (e < NE) ? ei[NE + e] : (e - NE);
    atomicAdd(&g_cnt[dst], 1);
}

__global__ void __launch_bounds__(1024) k_scan() {
    __shared__ int s[1024];
    __shared__ int s_off;
    int c = blockIdx.x, tid = threadIdx.x;
    int i = c * 1024 + tid;
    int v = (i < NN) ? g_cnt[i] : 0;
    s[tid] = v;
    __syncthreads();
    for (int off = 1; off < 1024; off <<= 1) {
        int t = (tid >= off) ? s[tid - off] : 0;
        __syncthreads();
        s[tid] += t;
        __syncthreads();
    }
    if (tid == 0) {
        int total = s[1023];
        g_agg[c] = total;
        __threadfence();
        atomicExch(&g_flag[c], 1);          // aggregate published
        int off = 0;
        for (int j = c - 1; j >= 0;) {
            int f;
            do { f = atomicAdd(&g_flag[j], 0); } while (f == 0);
            if (f == 2) { off += atomicAdd(&g_inc[j], 0); break; }
            off += atomicAdd(&g_agg[j], 0);
            j--;
        }
        g_inc[c] = off + total;
        __threadfence();
        atomicExch(&g_flag[c], 2);          // inclusive published
        s_off = off;
    }
    __syncthreads();
    if (i < NN) {
        g_rowptr[i] = s_off + s[tid] - v;   // exclusive prefix
        g_cur[i] = 0;
    }
    if (c == 0 && tid == 0) g_rowptr[NN] = ET;
}

__global__ void k_scatter(const int* __restrict__ ei) {
    int e = blockIdx.x * blockDim.x + threadIdx.x;
    if (e >= ET) return;
    int src, dst;
    if (e < NE) { src = ei[e]; dst = ei[NE + e]; }
    else        { src = dst = e - NE; }
    int pos = atomicAdd(&g_cur[dst], 1);
    g_csrc[g_rowptr[dst] + pos] = src;
}

// ---------------------------------------------------------------------------
// Fused GAT layer, plain-softmax (no max shift: logit sigma ~1, max < ~7,
// exp(d)/sum(exp(d)) identical to the shifted form), packed f32x2 math,
// packed butterfly reduce + one exp per lane, 4 rows in flight.
// 16 lanes own one dst node (64 ch = 2 x f32x2 per lane).
// ---------------------------------------------------------------------------
__device__ __forceinline__ void logits(
    ulonglong2 xs, ulonglong2 xd, u64 A0P, u64 A0Q, u64 A1P, u64 A1Q,
    u64 C06, u64 C04, float& d0, float& d1)
{
    u64 uP = FADD2(xs.x, xd.x), uQ = FADD2(xs.y, xd.y);
    u64 lP = FFMA2(uP, C06, FMUL2(FABS2(uP), C04));   // leaky_relu(0.2)
    u64 lQ = FFMA2(uQ, C06, FMUL2(FABS2(uQ), C04));
    u64 t0 = FFMA2(lP, A0P, FMUL2(lQ, A0Q));
    u64 t1 = FFMA2(lP, A1P, FMUL2(lQ, A1Q));
    float a, b;
    UPK(t0, a, b); d0 = a + b;
    UPK(t1, a, b); d1 = a + b;
}

// Reduce 4 values over the 16-lane group with lane-packing (8 shfl),
// exponentiate once per lane, broadcast the 4 exps (4 shfl).
__device__ __forceinline__ void redexp(
    int lane, float dA0, float dA1, float dB0, float dB1,
    float& pA0, float& pA1, float& pB0, float& pB1)
{
    const unsigned FM = 0xffffffffu;
    float tA0 = dA0 + __shfl_xor_sync(FM, dA0, 8, 16);
    float tA1 = dA1 + __shfl_xor_sync(FM, dA1, 8, 16);
    float tB0 = dB0 + __shfl_xor_sync(FM, dB0, 8, 16);
    float tB1 = dB1 + __shfl_xor_sync(FM, dB1, 8, 16);
    float u0 = (lane & 8) ? tB0 : tA0;    // bit3 selects edge
    float u1 = (lane & 8) ? tB1 : tA1;
    u0 += __shfl_xor_sync(FM, u0, 4, 16);
    u1 += __shfl_xor_sync(FM, u1, 4, 16);
    float w = (lane & 4) ? u1 : u0;       // bit2 selects head
    w += __shfl_xor_sync(FM, w, 2, 16);
    w += __shfl_xor_sync(FM, w, 1, 16);
    float ew = __expf(w);                 // one exp per lane
    pA0 = __shfl_sync(FM, ew, 0, 16);
    pA1 = __shfl_sync(FM, ew, 4, 16);
    pB0 = __shfl_sync(FM, ew, 8, 16);
    pB1 = __shfl_sync(FM, ew, 12, 16);
}

template<int LAYER>
__global__ void __launch_bounds__(256) k_layer(
    const float* __restrict__ h, float* __restrict__ hnext, float* __restrict__ acc,
    const float* __restrict__ attl, const float* __restrict__ biasl)
{
    int sub  = threadIdx.x >> 4;
    int lane = threadIdx.x & 15;
    int node = blockIdx.x * 16 + sub;          // grid*16 == NN exactly

    int start = g_rowptr[node];
    int deg   = g_rowptr[node + 1] - start;    // >= 1 (self loop)
    int dm1   = deg - 1;

    const ulonglong2* h8 = (const ulonglong2*)h;
    ulonglong2 xd = h8[node * 16 + lane];
    ulonglong2 A0 = ((const ulonglong2*)attl)[lane];
    ulonglong2 A1 = ((const ulonglong2*)(attl + NC))[lane];
    const u64 C06 = PK(0.6f, 0.6f), C04 = PK(0.4f, 0.4f);

    float s0 = 0.f, s1 = 0.f;
    u64 c0P = 0, c0Q = 0, c1P = 0, c1Q = 0;    // bit pattern 0 == (0.f,0.f)

    #define IDXC(k) g_csrc[start + (((k) < dm1) ? (k) : dm1)]

    // pipeline prologue: pairs (0,1) and (2,3) in flight, indices for (4,5)
    int i0 = IDXC(0), i1 = IDXC(1), i2 = IDXC(2), i3 = IDXC(3);
    ulonglong2 xA = h8[i0 * 16 + lane];
    ulonglong2 xB = xd, yA = xd, yB = xd;
    if (1 < deg) xB = h8[i1 * 16 + lane];
    if (2 < deg) yA = h8[i2 * 16 + lane];
    if (3 < deg) yB = h8[i3 * 16 + lane];
    int i4 = IDXC(4), i5 = IDXC(5);

    for (int e = 0; e < deg; e += 2) {
        // prefetch rows for pair e+4 (guarded; garbage never reaches valid slots)
        ulonglong2 zA = xd, zB = xd;
        if (e + 4 < deg) zA = h8[i4 * 16 + lane];
        if (e + 5 < deg) zB = h8[i5 * 16 + lane];
        i4 = IDXC(e + 6); i5 = IDXC(e + 7);

        float dA0, dA1, dB0, dB1;
        logits(xA, xd, A0.x, A0.y, A1.x, A1.y, C06, C04, dA0, dA1);
        logits(xB, xd, A0.x, A0.y, A1.x, A1.y, C06, C04, dB0, dB1);

        float pA0, pA1, pB0, pB1;
        redexp(lane, dA0, dA1, dB0, dB1, pA0, pA1, pB0, pB1);
        if (e + 1 >= deg) { pB0 = 0.f; pB1 = 0.f; }

        u64 P;
        P = PK(pA0, pA0); c0P = FFMA2(xA.x, P, c0P); c0Q = FFMA2(xA.y, P, c0Q);
        P = PK(pA1, pA1); c1P = FFMA2(xA.x, P, c1P); c1Q = FFMA2(xA.y, P, c1Q);
        s0 += pA0; s1 += pA1;
        P = PK(pB0, pB0); c0P = FFMA2(xB.x, P, c0P); c0Q = FFMA2(xB.y, P, c0Q);
        P = PK(pB1, pB1); c1P = FFMA2(xB.x, P, c1P); c1Q = FFMA2(xB.y, P, c1Q);
        s0 += pB0; s1 += pB1;

        xA = yA; xB = yB; yA = zA; yB = zB;
    }
    #undef IDXC

    float i0f = 0.5f / (s0 + 1e-16f), i1f = 0.5f / (s1 + 1e-16f);
    float4 b = ((const float4*)biasl)[lane];
    float c0x, c0y, c0z, c0w, c1x, c1y, c1z, c1w;
    UPK(c0P, c0x, c0y); UPK(c0Q, c0z, c0w);
    UPK(c1P, c1x, c1y); UPK(c1Q, c1z, c1w);
    float4 av;
    av.x = c0x * i0f + c1x * i1f + b.x;
    av.y = c0y * i0f + c1y * i1f + b.y;
    av.z = c0z * i0f + c1z * i1f + b.z;
    av.w = c0w * i0f + c1w * i1f + b.w;

    float xdx, xdy, xdz, xdw;
    UPK(xd.x, xdx, xdy); UPK(xd.y, xdz, xdw);

    float4* ap = (float4*)acc + node * 16 + lane;
    if (LAYER == 0) {
        ((float4*)hnext)[node * 16 + lane] = av;
        float4 o; o.x = xdx + av.x; o.y = xdy + av.y; o.z = xdz + av.z; o.w = xdw + av.w;
        *ap = o;                                   // acc = x + h1
    } else if (LAYER == 1) {
        ((float4*)hnext)[node * 16 + lane] = av;
        float4 o = *ap;
        o.x += av.x; o.y += av.y; o.z += av.z; o.w += av.w;
        *ap = o;
    } else {
        float4 o = *ap;                            // acc = (acc+h3)/4, no hnext
        o.x = (o.x + av.x) * 0.25f; o.y = (o.y + av.y) * 0.25f;
        o.z = (o.z + av.z) * 0.25f; o.w = (o.w + av.w) * 0.25f;
        *ap = o;
        // reset degree histogram for the next call (graph replay invariant)
        int t = blockIdx.x * blockDim.x + threadIdx.x;
        if (t < NN) g_cnt[t] = 0;
    }
}

// ---------------------------------------------------------------------------
// Launch (order puts k_layer<0> in ncu's captured slot #4)
// ---------------------------------------------------------------------------
extern "C" void kernel_launch(void* const* d_in, const int* in_sizes, int n_in,
                              void* d_out, int out_size) {
    const float* x    = (const float*)d_in[0];
    const int*   ei   = (const int*)d_in[1];
    const float* att  = (const float*)d_in[2];
    const float* bias = (const float*)d_in[3];
    float*       out  = (float*)d_out;

    float *hA, *hB;
    cudaGetSymbolAddress((void**)&hA, g_hA);
    cudaGetSymbolAddress((void**)&hB, g_hB);

    const int gridE = (ET + 255) / 256;
    const int gridL = NN / 16;                 // 3125, exact

    k_hist<<<gridE, 256>>>(ei);
    k_scan<<<NCHUNK, 1024>>>();
    k_scatter<<<gridE, 256>>>(ei);

    k_layer<0><<<gridL, 256>>>(x,  hA, out, att + 0 * 2 * NC, bias + 0 * NC);
    k_layer<1><<<gridL, 256>>>(hA, hB, out, att + 1 * 2 * NC, bias + 1 * NC);
    k_layer<2><<<gridL, 256>>>(hB, hA, out, att + 2 * 2 * NC, bias + 2 * NC);
}

// round 6
// speedup vs baseline: 1.1611x; 1.1611x over previous
#include <cuda_runtime.h>

#define NN 50000
#define NE 800000
#define ET (NE + NN)
#define NC 64
#define NCHUNK ((NN + 1023) / 1024)

// ---------------------------------------------------------------------------
// Static device scratch (allocation-free rule).
// ---------------------------------------------------------------------------
__device__ float g_hA[NN * NC];
__device__ float g_hB[NN * NC];
__device__ int   g_csrc[ET + 16];     // CSR src per edge (+16 zero pad: tail
                                      // never written, so over-reads are safe)
__device__ int   g_rowptr[NN + 1];
__device__ int   g_cnt[NN];           // zero at entry (zeroed by layer2 epilogue)
__device__ int   g_cur[NN];
__device__ int   g_agg[NCHUNK];       // decoupled-lookback state
__device__ int   g_inc[NCHUNK];
__device__ int   g_flag[NCHUNK];      // zeroed by k_hist each call

// ---------------------------------------------------------------------------
// CSR build: hist -> single-kernel scan (decoupled lookback) -> scatter
// ---------------------------------------------------------------------------
__global__ void k_hist(const int* __restrict__ ei) {
    int e = blockIdx.x * blockDim.x + threadIdx.x;
    if (e < NCHUNK) g_flag[e] = 0;
    if (e >= ET) return;
    int dst = (e < NE) ? ei[NE + e] : (e - NE);
    atomicAdd(&g_cnt[dst], 1);
}

__global__ void __launch_bounds__(1024) k_scan() {
    __shared__ int s[1024];
    __shared__ int s_off;
    int c = blockIdx.x, tid = threadIdx.x;
    int i = c * 1024 + tid;
    int v = (i < NN) ? g_cnt[i] : 0;
    s[tid] = v;
    __syncthreads();
    for (int off = 1; off < 1024; off <<= 1) {
        int t = (tid >= off) ? s[tid - off] : 0;
        __syncthreads();
        s[tid] += t;
        __syncthreads();
    }
    if (tid == 0) {
        int total = s[1023];
        g_agg[c] = total;
        __threadfence();
        atomicExch(&g_flag[c], 1);
        int off = 0;
        for (int j = c - 1; j >= 0;) {
            int f;
            do { f = atomicAdd(&g_flag[j], 0); } while (f == 0);
            if (f == 2) { off += atomicAdd(&g_inc[j], 0); break; }
            off += atomicAdd(&g_agg[j], 0);
            j--;
        }
        g_inc[c] = off + total;
        __threadfence();
        atomicExch(&g_flag[c], 2);
        s_off = off;
    }
    __syncthreads();
    if (i < NN) {
        g_rowptr[i] = s_off + s[tid] - v;
        g_cur[i] = 0;
    }
    if (c == 0 && tid == 0) g_rowptr[NN] = ET;
}

__global__ void k_scatter(const int* __restrict__ ei) {
    int e = blockIdx.x * blockDim.x + threadIdx.x;
    if (e >= ET) return;
    int src, dst;
    if (e < NE) { src = ei[e]; dst = ei[NE + e]; }
    else        { src = dst = e - NE; }
    int pos = atomicAdd(&g_cur[dst], 1);
    g_csrc[g_rowptr[dst] + pos] = src;
}

// ---------------------------------------------------------------------------
// Fused GAT layer. 16 lanes own one dst node (64 ch = 16 x float4).
// Plain softmax (no max shift: logit sigma ~1 so exp is far from overflow,
// and exp(d)/sum(exp(d)) is mathematically identical to the shifted form).
// Per 2 edges: scalar logits, packed 12-shfl butterfly, ONE exp per lane,
// 4 broadcasts. Guard-free prefetch pipeline via padded g_csrc.
// LAYER: 0 first (acc := x + h1), 1 middle (acc += av), 2 last (mean, no store).
// ---------------------------------------------------------------------------
__device__ __forceinline__ float lrelu(float v) { return fmaxf(v, 0.2f * v); }

template<int LAYER>
__global__ void __launch_bounds__(256) k_layer(
    const float* __restrict__ h, float* __restrict__ hnext, float* __restrict__ acc,
    const float* __restrict__ attl, const float* __restrict__ biasl)
{
    const unsigned FM = 0xffffffffu;
    int sub  = threadIdx.x >> 4;
    int lane = threadIdx.x & 15;
    int node = blockIdx.x * 16 + sub;          // grid*16 == NN exactly

    int start = g_rowptr[node];
    int deg   = g_rowptr[node + 1] - start;    // >= 1 (self loop)

    const float4* h4 = (const float4*)h;
    float4 xd = h4[node * 16 + lane];
    float4 a0 = ((const float4*)attl)[lane];
    float4 a1 = ((const float4*)(attl + NC))[lane];

    float sacc = 0.f;
    float4 c0 = make_float4(0.f, 0.f, 0.f, 0.f);
    float4 c1 = make_float4(0.f, 0.f, 0.f, 0.f);

    const int* cs = g_csrc + start;            // over-reads land in pad/neighbors
    int j0 = cs[0], j1 = cs[1];
    float4 xA = h4[j0 * 16 + lane];
    float4 xB = h4[j1 * 16 + lane];
    int j2 = cs[2], j3 = cs[3];

    for (int e = 0; e < deg; e += 2) {
        float4 nA = h4[j2 * 16 + lane];        // unconditional prefetch
        float4 nB = h4[j3 * 16 + lane];
        j2 = cs[e + 4]; j3 = cs[e + 5];

        // logits for both edges
        float vx, vy, vz, vw;
        vx = lrelu(xd.x + xA.x); vy = lrelu(xd.y + xA.y);
        vz = lrelu(xd.z + xA.z); vw = lrelu(xd.w + xA.w);
        float dA0 = vx * a0.x + vy * a0.y + vz * a0.z + vw * a0.w;
        float dA1 = vx * a1.x + vy * a1.y + vz * a1.z + vw * a1.w;
        vx = lrelu(xd.x + xB.x); vy = lrelu(xd.y + xB.y);
        vz = lrelu(xd.z + xB.z); vw = lrelu(xd.w + xB.w);
        float dB0 = vx * a0.x + vy * a0.y + vz * a0.z + vw * a0.w;
        float dB1 = vx * a1.x + vy * a1.y + vz * a1.z + vw * a1.w;

        // packed butterfly: 4 values -> 1 per lane-group, one exp per lane
        dA0 += __shfl_xor_sync(FM, dA0, 8, 16);
        dA1 += __shfl_xor_sync(FM, dA1, 8, 16);
        dB0 += __shfl_xor_sync(FM, dB0, 8, 16);
        dB1 += __shfl_xor_sync(FM, dB1, 8, 16);
        float u0 = (lane & 8) ? dB0 : dA0;     // bit3 selects edge
        float u1 = (lane & 8) ? dB1 : dA1;
        u0 += __shfl_xor_sync(FM, u0, 4, 16);
        u1 += __shfl_xor_sync(FM, u1, 4, 16);
        float w = (lane & 4) ? u1 : u0;        // bit2 selects head
        w += __shfl_xor_sync(FM, w, 2, 16);
        w += __shfl_xor_sync(FM, w, 1, 16);
        float ew = __expf(w);

        bool bval = (e + 1 < deg);
        sacc += (bval || lane < 8) ? ew : 0.f; // per-lane partial denominator

        float pA0 = __shfl_sync(FM, ew, 0, 16);
        float pA1 = __shfl_sync(FM, ew, 4, 16);
        float pB0 = __shfl_sync(FM, ew, 8, 16);
        float pB1 = __shfl_sync(FM, ew, 12, 16);
        if (!bval) { pB0 = 0.f; pB1 = 0.f; }

        c0.x += xA.x * pA0 + xB.x * pB0;  c0.y += xA.y * pA0 + xB.y * pB0;
        c0.z += xA.z * pA0 + xB.z * pB0;  c0.w += xA.w * pA0 + xB.w * pB0;
        c1.x += xA.x * pA1 + xB.x * pB1;  c1.y += xA.y * pA1 + xB.y * pB1;
        c1.z += xA.z * pA1 + xB.z * pB1;  c1.w += xA.w * pA1 + xB.w * pB1;

        xA = nA; xB = nB;
    }

    // finalize denominators: lanes 0-7 hold head0-type partials split A/B on bit3
    float sO = sacc + __shfl_xor_sync(FM, sacc, 8, 16);
    float sX = __shfl_xor_sync(FM, sO, 4, 16);
    float s0 = (lane & 4) ? sX : sO;
    float s1 = (lane & 4) ? sO : sX;

    float i0 = 0.5f / (s0 + 1e-16f), i1 = 0.5f / (s1 + 1e-16f);
    float4 b = ((const float4*)biasl)[lane];
    float4 av;
    av.x = c0.x * i0 + c1.x * i1 + b.x;
    av.y = c0.y * i0 + c1.y * i1 + b.y;
    av.z = c0.z * i0 + c1.z * i1 + b.z;
    av.w = c0.w * i0 + c1.w * i1 + b.w;

    float4* ap = (float4*)acc + node * 16 + lane;
    if (LAYER == 0) {
        ((float4*)hnext)[node * 16 + lane] = av;
        float4 o; o.x = xd.x + av.x; o.y = xd.y + av.y; o.z = xd.z + av.z; o.w = xd.w + av.w;
        *ap = o;                               // acc = x + h1
    } else if (LAYER == 1) {
        ((float4*)hnext)[node * 16 + lane] = av;
        float4 o = *ap;
        o.x += av.x; o.y += av.y; o.z += av.z; o.w += av.w;
        *ap = o;
    } else {
        float4 o = *ap;                        // acc = (acc + h3) / 4
        o.x = (o.x + av.x) * 0.25f; o.y = (o.y + av.y) * 0.25f;
        o.z = (o.z + av.z) * 0.25f; o.w = (o.w + av.w) * 0.25f;
        *ap = o;
        int t = blockIdx.x * blockDim.x + threadIdx.x;
        if (t < NN) g_cnt[t] = 0;              // reset histogram for next replay
    }
}

// ---------------------------------------------------------------------------
// Launch
// ---------------------------------------------------------------------------
extern "C" void kernel_launch(void* const* d_in, const int* in_sizes, int n_in,
                              void* d_out, int out_size) {
    const float* x    = (const float*)d_in[0];
    const int*   ei   = (const int*)d_in[1];
    const float* att  = (const float*)d_in[2];
    const float* bias = (const float*)d_in[3];
    float*       out  = (float*)d_out;

    float *hA, *hB;
    cudaGetSymbolAddress((void**)&hA, g_hA);
    cudaGetSymbolAddress((void**)&hB, g_hB);

    const int gridE = (ET + 255) / 256;
    const int gridL = NN / 16;                 // 3125, exact

    k_hist<<<gridE, 256>>>(ei);
    k_scan<<<NCHUNK, 1024>>>();
    k_scatter<<<gridE, 256>>>(ei);

    k_layer<0><<<gridL, 256>>>(x,  hA, out, att + 0 * 2 * NC, bias + 0 * NC);
    k_layer<1><<<gridL, 256>>>(hA, hB, out, att + 1 * 2 * NC, bias + 1 * NC);
    k_layer<2><<<gridL, 256>>>(hB, hA, out, att + 2 * 2 * NC, bias + 2 * NC);
}

// round 7
// speedup vs baseline: 1.2691x; 1.0930x over previous
#include <cuda_runtime.h>

#define NN 50000
#define NE 800000
#define ET (NE + NN)
#define NC 64
#define NCHUNK ((NN + 1023) / 1024)
#define NBIN 64

// ---------------------------------------------------------------------------
// Static device scratch (allocation-free rule).
// ---------------------------------------------------------------------------
__device__ float g_hA[NN * NC];
__device__ float g_hB[NN * NC];
__device__ int   g_csrc[ET + 16];     // CSR: src BYTE offsets (src*256), +16 pad
__device__ int   g_rowptr[NN + 1];
__device__ int   g_cnt[NN];           // zero at entry (zeroed by layer2 epilogue)
__device__ int   g_cur[NN];
__device__ int   g_agg[NCHUNK];       // decoupled-lookback state
__device__ int   g_inc[NCHUNK];
__device__ int   g_flag[NCHUNK];      // zeroed by k_hist each call
__device__ int   g_dcnt[NBIN];        // degree histogram (zeroed by k_hist)
__device__ int   g_doff[NBIN];
__device__ int   g_dcur[NBIN];
__device__ int   g_perm[NN];          // nodes sorted by degree bin

// ---------------------------------------------------------------------------
// CSR build: hist -> lookback scan (+deg hist) -> bin scan -> scatter (+perm)
// ---------------------------------------------------------------------------
__global__ void k_hist(const int* __restrict__ ei) {
    int e = blockIdx.x * blockDim.x + threadIdx.x;
    if (e < NCHUNK) g_flag[e] = 0;
    if (e < NBIN) g_dcnt[e] = 0;
    if (e >= ET) return;
    int dst = (e < NE) ? ei[NE + e] : (e - NE);
    atomicAdd(&g_cnt[dst], 1);
}

__global__ void __launch_bounds__(1024) k_scan() {
    __shared__ int s[1024];
    __shared__ int s_off;
    int c = blockIdx.x, tid = threadIdx.x;
    int i = c * 1024 + tid;
    int v = (i < NN) ? g_cnt[i] : 0;
    if (i < NN) atomicAdd(&g_dcnt[v < NBIN ? v : NBIN - 1], 1);   // degree bins
    s[tid] = v;
    __syncthreads();
    for (int off = 1; off < 1024; off <<= 1) {
        int t = (tid >= off) ? s[tid - off] : 0;
        __syncthreads();
        s[tid] += t;
        __syncthreads();
    }
    if (tid == 0) {
        int total = s[1023];
        g_agg[c] = total;
        __threadfence();
        atomicExch(&g_flag[c], 1);
        int off = 0;
        for (int j = c - 1; j >= 0;) {
            int f;
            do { f = atomicAdd(&g_flag[j], 0); } while (f == 0);
            if (f == 2) { off += atomicAdd(&g_inc[j], 0); break; }
            off += atomicAdd(&g_agg[j], 0);
            j--;
        }
        g_inc[c] = off + total;
        __threadfence();
        atomicExch(&g_flag[c], 2);
        s_off = off;
    }
    __syncthreads();
    if (i < NN) {
        g_rowptr[i] = s_off + s[tid] - v;
        g_cur[i] = 0;
    }
    if (c == 0 && tid == 0) g_rowptr[NN] = ET;
}

__global__ void k_dscan() {       // 64 threads, 1 block: bin offsets
    __shared__ int s[NBIN];
    int t = threadIdx.x;
    int v = g_dcnt[t];
    s[t] = v;
    __syncthreads();
    for (int off = 1; off < NBIN; off <<= 1) {
        int u = (t >= off) ? s[t - off] : 0;
        __syncthreads();
        s[t] += u;
        __syncthreads();
    }
    g_doff[t] = s[t] - v;
    g_dcur[t] = 0;
}

__global__ void k_scatter(const int* __restrict__ ei) {
    int e = blockIdx.x * blockDim.x + threadIdx.x;
    if (e < NN) {                 // build degree-binned permutation
        int deg = g_rowptr[e + 1] - g_rowptr[e];
        int b = deg < NBIN ? deg : NBIN - 1;
        int p = atomicAdd(&g_dcur[b], 1);
        g_perm[g_doff[b] + p] = e;
    }
    if (e >= ET) return;
    int src, dst;
    if (e < NE) { src = ei[e]; dst = ei[NE + e]; }
    else        { src = dst = e - NE; }
    int pos = atomicAdd(&g_cur[dst], 1);
    g_csrc[g_rowptr[dst] + pos] = src << 8;   // byte offset (256 B/row)
}

// ---------------------------------------------------------------------------
// Fused GAT layer. 16 lanes own one dst node (64 ch = 16 x float4), nodes
// taken in degree-sorted order via g_perm so warp subgroups have equal work.
// Plain softmax (no max shift: logit sigma ~1, far from fp32 exp range;
// exp(d)/sum(exp(d)) identical to shifted form). Per 2 edges: scalar logits,
// packed 12-shfl butterfly, ONE exp per lane, 4 broadcasts.
// ---------------------------------------------------------------------------
__device__ __forceinline__ float lrelu(float v) { return fmaxf(v, 0.2f * v); }

template<int LAYER>
__global__ void __launch_bounds__(256) k_layer(
    const float* __restrict__ h, float* __restrict__ hnext, float* __restrict__ acc,
    const float* __restrict__ attl, const float* __restrict__ biasl)
{
    const unsigned FM = 0xffffffffu;
    int sub  = threadIdx.x >> 4;
    int lane = threadIdx.x & 15;
    int gi   = blockIdx.x * 16 + sub;          // grid*16 == NN exactly
    int node = g_perm[gi];                     // uniform across subgroup

    int start = g_rowptr[node];
    int deg   = g_rowptr[node + 1] - start;    // >= 1 (self loop)

    const char* hb = (const char*)h;
    int lane16 = lane * 16;
    float4 xd = *(const float4*)(hb + (size_t)node * 256 + lane16);
    float4 a0 = ((const float4*)attl)[lane];
    float4 a1 = ((const float4*)(attl + NC))[lane];

    float sacc = 0.f;
    float4 c0 = make_float4(0.f, 0.f, 0.f, 0.f);
    float4 c1 = make_float4(0.f, 0.f, 0.f, 0.f);

    const int* cs = g_csrc + start;            // over-reads hit pad/neighbors
    int j0 = cs[0], j1 = cs[1];
    float4 xA = *(const float4*)(hb + j0 + lane16);
    float4 xB = *(const float4*)(hb + j1 + lane16);
    int j2 = cs[2], j3 = cs[3];

    for (int e = 0; e < deg; e += 2) {
        float4 nA = *(const float4*)(hb + j2 + lane16);   // unconditional prefetch
        float4 nB = *(const float4*)(hb + j3 + lane16);
        j2 = cs[e + 4]; j3 = cs[e + 5];

        float vx, vy, vz, vw;
        vx = lrelu(xd.x + xA.x); vy = lrelu(xd.y + xA.y);
        vz = lrelu(xd.z + xA.z); vw = lrelu(xd.w + xA.w);
        float dA0 = vx * a0.x + vy * a0.y + vz * a0.z + vw * a0.w;
        float dA1 = vx * a1.x + vy * a1.y + vz * a1.z + vw * a1.w;
        vx = lrelu(xd.x + xB.x); vy = lrelu(xd.y + xB.y);
        vz = lrelu(xd.z + xB.z); vw = lrelu(xd.w + xB.w);
        float dB0 = vx * a0.x + vy * a0.y + vz * a0.z + vw * a0.w;
        float dB1 = vx * a1.x + vy * a1.y + vz * a1.z + vw * a1.w;

        // packed butterfly: 4 sums -> 1 per lane, one exp per lane
        dA0 += __shfl_xor_sync(FM, dA0, 8, 16);
        dA1 += __shfl_xor_sync(FM, dA1, 8, 16);
        dB0 += __shfl_xor_sync(FM, dB0, 8, 16);
        dB1 += __shfl_xor_sync(FM, dB1, 8, 16);
        float u0 = (lane & 8) ? dB0 : dA0;     // bit3 selects edge
        float u1 = (lane & 8) ? dB1 : dA1;
        u0 += __shfl_xor_sync(FM, u0, 4, 16);
        u1 += __shfl_xor_sync(FM, u1, 4, 16);
        float w = (lane & 4) ? u1 : u0;        // bit2 selects head
        w += __shfl_xor_sync(FM, w, 2, 16);
        w += __shfl_xor_sync(FM, w, 1, 16);
        float ew = __expf(w);

        bool bval = (e + 1 < deg);
        sacc += (bval || lane < 8) ? ew : 0.f;

        float pA0 = __shfl_sync(FM, ew, 0, 16);
        float pA1 = __shfl_sync(FM, ew, 4, 16);
        float pB0 = __shfl_sync(FM, ew, 8, 16);
        float pB1 = __shfl_sync(FM, ew, 12, 16);
        if (!bval) { pB0 = 0.f; pB1 = 0.f; }

        c0.x += xA.x * pA0 + xB.x * pB0;  c0.y += xA.y * pA0 + xB.y * pB0;
        c0.z += xA.z * pA0 + xB.z * pB0;  c0.w += xA.w * pA0 + xB.w * pB0;
        c1.x += xA.x * pA1 + xB.x * pB1;  c1.y += xA.y * pA1 + xB.y * pB1;
        c1.z += xA.z * pA1 + xB.z * pB1;  c1.w += xA.w * pA1 + xB.w * pB1;

        xA = nA; xB = nB;
    }

    // finalize denominators (lane-partial layout: bit3 = edge, bit2 = head)
    float sO = sacc + __shfl_xor_sync(FM, sacc, 8, 16);
    float sX = __shfl_xor_sync(FM, sO, 4, 16);
    float s0 = (lane & 4) ? sX : sO;
    float s1 = (lane & 4) ? sO : sX;

    float i0 = 0.5f / (s0 + 1e-16f), i1 = 0.5f / (s1 + 1e-16f);
    float4 b = ((const float4*)biasl)[lane];
    float4 av;
    av.x = c0.x * i0 + c1.x * i1 + b.x;
    av.y = c0.y * i0 + c1.y * i1 + b.y;
    av.z = c0.z * i0 + c1.z * i1 + b.z;
    av.w = c0.w * i0 + c1.w * i1 + b.w;

    float4* ap = (float4*)acc + node * 16 + lane;
    if (LAYER == 0) {
        ((float4*)hnext)[node * 16 + lane] = av;
        float4 o; o.x = xd.x + av.x; o.y = xd.y + av.y; o.z = xd.z + av.z; o.w = xd.w + av.w;
        *ap = o;                               // acc = x + h1
    } else if (LAYER == 1) {
        ((float4*)hnext)[node * 16 + lane] = av;
        float4 o = *ap;
        o.x += av.x; o.y += av.y; o.z += av.z; o.w += av.w;
        *ap = o;
    } else {
        float4 o = *ap;                        // acc = (acc + h3) / 4
        o.x = (o.x + av.x) * 0.25f; o.y = (o.y + av.y) * 0.25f;
        o.z = (o.z + av.z) * 0.25f; o.w = (o.w + av.w) * 0.25f;
        *ap = o;
        int t = blockIdx.x * blockDim.x + threadIdx.x;
        if (t < NN) g_cnt[t] = 0;              // reset histogram for next replay
    }
}

// ---------------------------------------------------------------------------
// Launch
// ---------------------------------------------------------------------------
extern "C" void kernel_launch(void* const* d_in, const int* in_sizes, int n_in,
                              void* d_out, int out_size) {
    const float* x    = (const float*)d_in[0];
    const int*   ei   = (const int*)d_in[1];
    const float* att  = (const float*)d_in[2];
    const float* bias = (const float*)d_in[3];
    float*       out  = (float*)d_out;

    float *hA, *hB;
    cudaGetSymbolAddress((void**)&hA, g_hA);
    cudaGetSymbolAddress((void**)&hB, g_hB);

    const int gridE = (ET + 255) / 256;
    const int gridL = NN / 16;                 // 3125, exact

    k_hist<<<gridE, 256>>>(ei);
    k_scan<<<NCHUNK, 1024>>>();
    k_dscan<<<1, NBIN>>>();
    k_scatter<<<gridE, 256>>>(ei);

    k_layer<0><<<gridL, 256>>>(x,  hA, out, att + 0 * 2 * NC, bias + 0 * NC);
    k_layer<1><<<gridL, 256>>>(hA, hB, out, att + 1 * 2 * NC, bias + 1 * NC);
    k_layer<2><<<gridL, 256>>>(hB, hA, out, att + 2 * 2 * NC, bias + 2 * NC);
}

// round 8
// speedup vs baseline: 1.2840x; 1.0118x over previous
#include <cuda_runtime.h>

#define NN 50000
#define NE 800000
#define ET (NE + NN)
#define NC 64
#define NCHUNK ((NN + 1023) / 1024)
#define NBIN 64

// ---------------------------------------------------------------------------
// Static device scratch (allocation-free rule).
// ---------------------------------------------------------------------------
__device__ float g_hA[NN * NC];
__device__ float g_hB[NN * NC];
__device__ int   g_csrc[ET + 16];     // CSR: src BYTE offsets (src*256), +16 pad
__device__ int   g_rank[ET];          // per-edge rank within its dst (from hist)
__device__ int   g_rowptr[NN + 1];
__device__ int   g_cnt[NN];           // zero at entry (zeroed by layer2 epilogue)
__device__ int   g_agg[NCHUNK];       // decoupled-lookback state
__device__ int   g_inc[NCHUNK];
__device__ int   g_flag[NCHUNK];      // zeroed by k_hist each call
__device__ int   g_dcnt[NBIN];        // degree histogram (zeroed by k_hist)
__device__ int   g_doff[NBIN];
__device__ int   g_dcur[NBIN];
__device__ int   g_perm[NN];          // nodes sorted by degree bin

// ---------------------------------------------------------------------------
// CSR build: hist(+rank) -> lookback scan(+deg bins) -> bin scan -> scatter
// ---------------------------------------------------------------------------
__global__ void k_hist(const int* __restrict__ ei) {
    int e = blockIdx.x * blockDim.x + threadIdx.x;
    if (e < NCHUNK) g_flag[e] = 0;
    if (e < NBIN) g_dcnt[e] = 0;
    if (e >= ET) return;
    int dst = (e < NE) ? ei[NE + e] : (e - NE);
    g_rank[e] = atomicAdd(&g_cnt[dst], 1);    // rank = arrival order within dst
}

__global__ void __launch_bounds__(1024) k_scan() {
    __shared__ int s[1024];
    __shared__ int s_off;
    int c = blockIdx.x, tid = threadIdx.x;
    int i = c * 1024 + tid;
    int v = (i < NN) ? g_cnt[i] : 0;
    if (i < NN) atomicAdd(&g_dcnt[v < NBIN ? v : NBIN - 1], 1);   // degree bins
    s[tid] = v;
    __syncthreads();
    for (int off = 1; off < 1024; off <<= 1) {
        int t = (tid >= off) ? s[tid - off] : 0;
        __syncthreads();
        s[tid] += t;
        __syncthreads();
    }
    if (tid == 0) {
        int total = s[1023];
        g_agg[c] = total;
        __threadfence();
        atomicExch(&g_flag[c], 1);
        int off = 0;
        for (int j = c - 1; j >= 0;) {
            int f;
            do { f = atomicAdd(&g_flag[j], 0); } while (f == 0);
            if (f == 2) { off += atomicAdd(&g_inc[j], 0); break; }
            off += atomicAdd(&g_agg[j], 0);
            j--;
        }
        g_inc[c] = off + total;
        __threadfence();
        atomicExch(&g_flag[c], 2);
        s_off = off;
    }
    __syncthreads();
    if (i < NN) g_rowptr[i] = s_off + s[tid] - v;
    if (c == 0 && tid == 0) g_rowptr[NN] = ET;
}

__global__ void k_dscan() {       // 64 threads, 1 block: bin offsets
    __shared__ int s[NBIN];
    int t = threadIdx.x;
    int v = g_dcnt[t];
    s[t] = v;
    __syncthreads();
    for (int off = 1; off < NBIN; off <<= 1) {
        int u = (t >= off) ? s[t - off] : 0;
        __syncthreads();
        s[t] += u;
        __syncthreads();
    }
    g_doff[t] = s[t] - v;
    g_dcur[t] = 0;
}

// No atomics on the edge path: rank was captured in k_hist.
__global__ void k_scatter(const int* __restrict__ ei) {
    int e = blockIdx.x * blockDim.x + threadIdx.x;
    if (e < NN) {                 // build degree-binned permutation (50k atomics)
        int deg = g_rowptr[e + 1] - g_rowptr[e];
        int b = deg < NBIN ? deg : NBIN - 1;
        int p = atomicAdd(&g_dcur[b], 1);
        g_perm[g_doff[b] + p] = e;
    }
    if (e >= ET) return;
    int src, dst;
    if (e < NE) { src = ei[e]; dst = ei[NE + e]; }
    else        { src = dst = e - NE; }
    g_csrc[g_rowptr[dst] + g_rank[e]] = src << 8;   // byte offset (256 B/row)
}

// ---------------------------------------------------------------------------
// Fused GAT layer. 16 lanes own one dst node (64 ch = 16 x float4), nodes
// taken in degree-sorted order via g_perm so warp subgroups have equal work.
// Plain softmax (no max shift: logit sigma ~1, far from fp32 exp range;
// exp(d)/sum(exp(d)) identical to shifted form). Per 2 edges: scalar logits,
// packed 12-shfl butterfly, ONE exp per lane, 4 broadcasts.
// ---------------------------------------------------------------------------
__device__ __forceinline__ float lrelu(float v) { return fmaxf(v, 0.2f * v); }

template<int LAYER>
__global__ void __launch_bounds__(256) k_layer(
    const float* __restrict__ h, float* __restrict__ hnext, float* __restrict__ acc,
    const float* __restrict__ attl, const float* __restrict__ biasl)
{
    const unsigned FM = 0xffffffffu;
    int sub  = threadIdx.x >> 4;
    int lane = threadIdx.x & 15;
    int gi   = blockIdx.x * 16 + sub;          // grid*16 == NN exactly
    int node = g_perm[gi];                     // uniform across subgroup

    int start = g_rowptr[node];
    int deg   = g_rowptr[node + 1] - start;    // >= 1 (self loop)

    const char* hb = (const char*)h;
    int lane16 = lane * 16;
    float4 xd = *(const float4*)(hb + (size_t)node * 256 + lane16);
    float4 a0 = ((const float4*)attl)[lane];
    float4 a1 = ((const float4*)(attl + NC))[lane];

    float sacc = 0.f;
    float4 c0 = make_float4(0.f, 0.f, 0.f, 0.f);
    float4 c1 = make_float4(0.f, 0.f, 0.f, 0.f);

    const int* cs = g_csrc + start;            // over-reads hit pad/neighbors
    int j0 = cs[0], j1 = cs[1];
    float4 xA = *(const float4*)(hb + j0 + lane16);
    float4 xB = *(const float4*)(hb + j1 + lane16);
    int j2 = cs[2], j3 = cs[3];

    for (int e = 0; e < deg; e += 2) {
        float4 nA = *(const float4*)(hb + j2 + lane16);   // unconditional prefetch
        float4 nB = *(const float4*)(hb + j3 + lane16);
        j2 = cs[e + 4]; j3 = cs[e + 5];

        float vx, vy, vz, vw;
        vx = lrelu(xd.x + xA.x); vy = lrelu(xd.y + xA.y);
        vz = lrelu(xd.z + xA.z); vw = lrelu(xd.w + xA.w);
        float dA0 = vx * a0.x + vy * a0.y + vz * a0.z + vw * a0.w;
        float dA1 = vx * a1.x + vy * a1.y + vz * a1.z + vw * a1.w;
        vx = lrelu(xd.x + xB.x); vy = lrelu(xd.y + xB.y);
        vz = lrelu(xd.z + xB.z); vw = lrelu(xd.w + xB.w);
        float dB0 = vx * a0.x + vy * a0.y + vz * a0.z + vw * a0.w;
        float dB1 = vx * a1.x + vy * a1.y + vz * a1.z + vw * a1.w;

        // packed butterfly: 4 sums -> 1 per lane, one exp per lane
        dA0 += __shfl_xor_sync(FM, dA0, 8, 16);
        dA1 += __shfl_xor_sync(FM, dA1, 8, 16);
        dB0 += __shfl_xor_sync(FM, dB0, 8, 16);
        dB1 += __shfl_xor_sync(FM, dB1, 8, 16);
        float u0 = (lane & 8) ? dB0 : dA0;     // bit3 selects edge
        float u1 = (lane & 8) ? dB1 : dA1;
        u0 += __shfl_xor_sync(FM, u0, 4, 16);
        u1 += __shfl_xor_sync(FM, u1, 4, 16);
        float w = (lane & 4) ? u1 : u0;        // bit2 selects head
        w += __shfl_xor_sync(FM, w, 2, 16);
        w += __shfl_xor_sync(FM, w, 1, 16);
        float ew = __expf(w);

        bool bval = (e + 1 < deg);
        sacc += (bval || lane < 8) ? ew : 0.f;

        float pA0 = __shfl_sync(FM, ew, 0, 16);
        float pA1 = __shfl_sync(FM, ew, 4, 16);
        float pB0 = __shfl_sync(FM, ew, 8, 16);
        float pB1 = __shfl_sync(FM, ew, 12, 16);
        if (!bval) { pB0 = 0.f; pB1 = 0.f; }

        c0.x += xA.x * pA0 + xB.x * pB0;  c0.y += xA.y * pA0 + xB.y * pB0;
        c0.z += xA.z * pA0 + xB.z * pB0;  c0.w += xA.w * pA0 + xB.w * pB0;
        c1.x += xA.x * pA1 + xB.x * pB1;  c1.y += xA.y * pA1 + xB.y * pB1;
        c1.z += xA.z * pA1 + xB.z * pB1;  c1.w += xA.w * pA1 + xB.w * pB1;

        xA = nA; xB = nB;
    }

    // finalize denominators (lane-partial layout: bit3 = edge, bit2 = head)
    float sO = sacc + __shfl_xor_sync(FM, sacc, 8, 16);
    float sX = __shfl_xor_sync(FM, sO, 4, 16);
    float s0 = (lane & 4) ? sX : sO;
    float s1 = (lane & 4) ? sO : sX;

    float i0 = 0.5f / (s0 + 1e-16f), i1 = 0.5f / (s1 + 1e-16f);
    float4 b = ((const float4*)biasl)[lane];
    float4 av;
    av.x = c0.x * i0 + c1.x * i1 + b.x;
    av.y = c0.y * i0 + c1.y * i1 + b.y;
    av.z = c0.z * i0 + c1.z * i1 + b.z;
    av.w = c0.w * i0 + c1.w * i1 + b.w;

    float4* ap = (float4*)acc + node * 16 + lane;
    if (LAYER == 0) {
        ((float4*)hnext)[node * 16 + lane] = av;
        float4 o; o.x = xd.x + av.x; o.y = xd.y + av.y; o.z = xd.z + av.z; o.w = xd.w + av.w;
        *ap = o;                               // acc = x + h1
    } else if (LAYER == 1) {
        ((float4*)hnext)[node * 16 + lane] = av;
        float4 o = *ap;
        o.x += av.x; o.y += av.y; o.z += av.z; o.w += av.w;
        *ap = o;
    } else {
        float4 o = *ap;                        // acc = (acc + h3) / 4
        o.x = (o.x + av.x) * 0.25f; o.y = (o.y + av.y) * 0.25f;
        o.z = (o.z + av.z) * 0.25f; o.w = (o.w + av.w) * 0.25f;
        *ap = o;
        int t = blockIdx.x * blockDim.x + threadIdx.x;
        if (t < NN) g_cnt[t] = 0;              // reset histogram for next replay
    }
}

// ---------------------------------------------------------------------------
// Launch
// ---------------------------------------------------------------------------
extern "C" void kernel_launch(void* const* d_in, const int* in_sizes, int n_in,
                              void* d_out, int out_size) {
    const float* x    = (const float*)d_in[0];
    const int*   ei   = (const int*)d_in[1];
    const float* att  = (const float*)d_in[2];
    const float* bias = (const float*)d_in[3];
    float*       out  = (float*)d_out;

    float *hA, *hB;
    cudaGetSymbolAddress((void**)&hA, g_hA);
    cudaGetSymbolAddress((void**)&hB, g_hB);

    const int gridE = (ET + 255) / 256;
    const int gridL = NN / 16;                 // 3125, exact

    k_hist<<<gridE, 256>>>(ei);
    k_scan<<<NCHUNK, 1024>>>();
    k_dscan<<<1, NBIN>>>();
    k_scatter<<<gridE, 256>>>(ei);

    k_layer<0><<<gridL, 256>>>(x,  hA, out, att + 0 * 2 * NC, bias + 0 * NC);
    k_layer<1><<<gridL, 256>>>(hA, hB, out, att + 1 * 2 * NC, bias + 1 * NC);
    k_layer<2><<<gridL, 256>>>(hB, hA, out, att + 2 * 2 * NC, bias + 2 * NC);
}